// round 2
// baseline (speedup 1.0000x reference)
#include <cuda_runtime.h>

typedef unsigned long long u64;

// Problem constants (fixed for this problem instance)
constexpr int NX      = 8388608;   // len(x)
constexpr int TAPS3   = 341;       // taps per polyphase branch (1023/3)
constexpr int S_PAD   = 176;       // pair-steps, padded to multiple of 8 (171 real)
constexpr int R       = 8;         // outputs per thread (same phase, consecutive q)
constexpr int G       = 128;       // threads per phase group
constexpr int THREADS = 384;       // 3 phases * G
constexpr int QB      = G * R;     // 1024 q-values per block
constexpr int TILE_USED   = 1199;  // float2 pairs of x needed per block
constexpr int OUT_PER_BLK = 3 * QB; // 3072 outputs per block

// Packed filter: 3 variants (phase-subsequence x parity), each S_PAD float2.
// Variant v for output subsequence s_out = v covers:
//   v=0: p=1, rho=0 ; v=1: p=0, rho=1 ; v=2: p=2, rho=1
// F2[s] = ( hp[2s+rho], hp[2s+rho-1] ), hp[j] = 3*h[p+3j] (0 outside [0,341))
__device__ float2 g_fpack[3 * S_PAD];

__global__ void prep_kernel(const float* __restrict__ h) {
    int i = blockIdx.x * blockDim.x + threadIdx.x;
    if (i >= 3 * S_PAD) return;
    int v = i / S_PAD, s = i % S_PAD;
    int p   = (v == 0) ? 1 : (v == 1 ? 0 : 2);
    int rho = (v == 0) ? 0 : 1;
    int jx = 2 * s + rho;
    int jy = jx - 1;
    float fx = (jx >= 0 && jx < TAPS3) ? 3.0f * h[p + 3 * jx] : 0.0f;
    float fy = (jy >= 0 && jy < TAPS3) ? 3.0f * h[p + 3 * jy] : 0.0f;
    g_fpack[i] = make_float2(fx, fy);
}

__device__ __forceinline__ int swz(int i) { return i ^ ((i >> 4) & 15); }

// Packed dual-fp32 FMA (sm_100+ only; ptxas emits FFMA2)
#define FFMA2(d, a, b) asm("fma.rn.f32x2 %0, %1, %2, %0;" : "+l"(d) : "l"(a), "l"(b))

__global__ __launch_bounds__(THREADS, 2)
void resample_kernel(const float* __restrict__ x, float* __restrict__ out) {
    // xs: swizzled x tile (float2 pairs); reused as output staging (3072 floats)
    __shared__ __align__(16) float2 xs[1536];        // 12288 B
    __shared__ __align__(16) float2 fsh[3 * S_PAD];  //  4224 B

    const int tid = threadIdx.x;
    const int Q0  = blockIdx.x * QB;
    const long long P0 = (long long)Q0 - 90;   // global pair index of tile[0]

    // Stage packed filter into shared
    for (int i = tid; i < 3 * S_PAD; i += THREADS) fsh[i] = g_fpack[i];

    // Stage x tile (zero-padded at array edges), swizzled
    const float2* x2 = reinterpret_cast<const float2*>(x);
    for (int i = tid; i < TILE_USED; i += THREADS) {
        long long u = P0 + i;
        float2 v = make_float2(0.0f, 0.0f);
        if (u >= 0 && u < (long long)(NX / 2)) v = __ldg(&x2[u]);
        xs[swz(i)] = v;
    }
    __syncthreads();

    const int sub = tid / G;                 // phase subsequence, warp-uniform
    const int g   = tid % G;
    const int lw  = g * R + (S_PAD - 1);     // local pair base (r=0, s=0 offset)

    const u64* xsu = reinterpret_cast<const u64*>(xs);
    const u64* fsu = reinterpret_cast<const u64*>(fsh) + sub * S_PAD;

    u64 W[R], acc[R];
#pragma unroll
    for (int r = 0; r < R; ++r) { acc[r] = 0ULL; W[r] = xsu[swz(lw + r)]; }

    // Main loop: per step s, acc_r += X2[lw + r - s] .* F2[s]
    for (int t = 0; t < S_PAD / R; ++t) {
#pragma unroll
        for (int k = 0; k < R; ++k) {
            const int s = t * R + k;
            const u64 fv = fsu[s];
#pragma unroll
            for (int r = 0; r < R; ++r) FFMA2(acc[r], W[r], fv);
            int li = lw - 1 - s;             // next (lowest) window element
            if (li < 0) li = 0;              // only hits on the final, unused step
            const u64 nv = xsu[swz(li)];
#pragma unroll
            for (int r = R - 1; r >= 1; --r) W[r] = W[r - 1];
            W[0] = nv;
        }
    }

    __syncthreads();   // done reading xs; reuse as output staging
    float* outsh = reinterpret_cast<float*>(xs);
#pragma unroll
    for (int r = 0; r < R; ++r) {
        float lo = __uint_as_float((unsigned)(acc[r] & 0xffffffffull));
        float hi = __uint_as_float((unsigned)(acc[r] >> 32));
        outsh[3 * (g * R + r) + sub] = lo + hi;   // m = 3q + sub, local
    }
    __syncthreads();

    // Coalesced float4 stream-out: block covers out[3*Q0 .. 3*Q0+3072)
    float4* dst = reinterpret_cast<float4*>(out + 3LL * Q0);
    const float4* src = reinterpret_cast<const float4*>(outsh);
    for (int i = tid; i < OUT_PER_BLK / 4; i += THREADS) dst[i] = src[i];
}

extern "C" void kernel_launch(void* const* d_in, const int* in_sizes, int n_in,
                              void* d_out, int out_size) {
    const float* x = (const float*)d_in[0];
    // d_in[1]=up(3), d_in[2]=down(2) — fixed for this problem
    const float* h = (const float*)d_in[3];
    float* out = (float*)d_out;

    prep_kernel<<<(3 * S_PAD + 127) / 128, 128>>>(h);
    const int blocks = out_size / OUT_PER_BLK;   // 12582912 / 3072 = 4096
    resample_kernel<<<blocks, THREADS>>>(x, out);
}

// round 5
// speedup vs baseline: 1.0312x; 1.0312x over previous
#include <cuda_runtime.h>

typedef unsigned long long u64;

// Problem constants (fixed for this problem instance)
constexpr int NX      = 8388608;   // len(x)
constexpr int TAPS3   = 341;       // taps per polyphase branch (1023/3)
constexpr int S_PAD   = 176;       // pair-steps, padded to multiple of 8 (171 real)
constexpr int R       = 8;         // outputs per thread (same phase, consecutive q)
constexpr int G       = 128;       // threads per phase group
constexpr int THREADS = 384;       // 3 phases * G
constexpr int QB      = G * R;     // 1024 q-values per block
constexpr int PADL    = 8;         // bottom zero-pad pairs (removes index clamp)
constexpr int TILE_USED   = 1199;  // float2 pairs of x needed per block
constexpr int TILE_TOT    = PADL + TILE_USED;  // 1207
constexpr int OUT_PER_BLK = 3 * QB; // 3072 outputs per block

// Packed filter: 3 variants (phase-subsequence x parity), each S_PAD float2.
//   v=0: p=1, rho=0 ; v=1: p=0, rho=1 ; v=2: p=2, rho=1
// F2[s] = ( hp[2s+rho], hp[2s+rho-1] ), hp[j] = 3*h[p+3j] (0 outside [0,341))
__device__ __align__(16) float2 g_fpack[3 * S_PAD];

__global__ void prep_kernel(const float* __restrict__ h) {
    int i = blockIdx.x * blockDim.x + threadIdx.x;
    if (i >= 3 * S_PAD) return;
    int v = i / S_PAD, s = i % S_PAD;
    int p   = (v == 0) ? 1 : (v == 1 ? 0 : 2);
    int rho = (v == 0) ? 0 : 1;
    int jx = 2 * s + rho;
    int jy = jx - 1;
    float fx = (jx >= 0 && jx < TAPS3) ? 3.0f * h[p + 3 * jx] : 0.0f;
    float fy = (jy >= 0 && jy < TAPS3) ? 3.0f * h[p + 3 * jy] : 0.0f;
    g_fpack[i] = make_float2(fx, fy);
}

// Byte-offset XOR swizzle: injects bits[7:11) into [3:7). For lanes at 64B
// stride this maps 16 consecutive lanes onto 16 distinct bank-pairs
// (conflict-free LDS.64), for any base. 3 ALU ops: IADD/SHF/LOP3.
__device__ __forceinline__ int swzb(int b) { return b ^ ((b >> 4) & 0x78); }

// Packed dual-fp32 FMA (sm_100+; ptxas emits FFMA2)
#define FFMA2(d, a, b) asm("fma.rn.f32x2 %0, %1, %2, %0;" : "+l"(d) : "l"(a), "l"(b))

__global__ __launch_bounds__(THREADS, 2)
void resample_kernel(const float* __restrict__ x, float* __restrict__ out) {
    // xs: swizzled x tile (u64 pairs); reused as output staging (3072 floats)
    __shared__ __align__(16) u64 xs[1536];   // 12288 B

    const int tid = threadIdx.x;
    const int Q0  = blockIdx.x * QB;
    const long long P0 = (long long)Q0 - 90;   // global pair index of tile slot PADL

    char* xsb = reinterpret_cast<char*>(xs);

    // Stage x tile (zero-padded at both edges), swizzled byte layout
    const float2* x2 = reinterpret_cast<const float2*>(x);
    for (int j = tid; j < TILE_TOT; j += THREADS) {
        long long u = P0 + (j - PADL);
        float2 v = make_float2(0.0f, 0.0f);
        if (u >= 0 && u < (long long)(NX / 2)) v = __ldg(&x2[u]);
        *reinterpret_cast<float2*>(xsb + swzb(j * 8)) = v;
    }
    __syncthreads();

    const int sub = tid / G;                 // phase subsequence, warp-uniform
    const int g   = tid % G;
    const int lw  = g * R + (S_PAD - 1);     // local pair base (r=0, s=0 offset)

    // Filter straight from global (4KB, L1-resident, broadcast = 1 sector/step)
    const u64* __restrict__ fgl =
        reinterpret_cast<const u64*>(g_fpack) + sub * S_PAD;

    u64 W[R], acc[R];
#pragma unroll
    for (int r = 0; r < R; ++r) {
        acc[r] = 0ULL;
        W[r] = *reinterpret_cast<const u64*>(xsb + swzb((PADL + lw + r) * 8));
    }

    // b0: pre-swizzle byte offset of the step-0 window refill element
    int b0 = (PADL + lw - 1) * 8;

    // Main loop: per step s, acc_r += X2[lw + r - s] .* F2[s]
    for (int t = 0; t < S_PAD / R; ++t) {
#pragma unroll
        for (int k = 0; k < R; ++k) {
            const u64 fv = __ldg(&fgl[t * R + k]);   // hoisted/batched by ptxas
#pragma unroll
            for (int r = 0; r < R; ++r) FFMA2(acc[r], W[r], fv);
            const u64 nv =
                *reinterpret_cast<const u64*>(xsb + swzb(b0 - 8 * k));
#pragma unroll
            for (int r = R - 1; r >= 1; --r) W[r] = W[r - 1];
            W[0] = nv;
        }
        b0 -= 8 * R;
    }

    __syncthreads();   // done reading xs; reuse as output staging
    float* outsh = reinterpret_cast<float*>(xs);
#pragma unroll
    for (int r = 0; r < R; ++r) {
        float lo = __uint_as_float((unsigned)(acc[r] & 0xffffffffull));
        float hi = __uint_as_float((unsigned)(acc[r] >> 32));
        outsh[3 * (g * R + r) + sub] = lo + hi;   // m = 3q + sub, local
    }
    __syncthreads();

    // Coalesced float4 stream-out: block covers out[3*Q0 .. 3*Q0+3072)
    float4* dst = reinterpret_cast<float4*>(out + 3LL * Q0);
    const float4* src = reinterpret_cast<const float4*>(outsh);
    for (int i = tid; i < OUT_PER_BLK / 4; i += THREADS) dst[i] = src[i];
}

extern "C" void kernel_launch(void* const* d_in, const int* in_sizes, int n_in,
                              void* d_out, int out_size) {
    const float* x = (const float*)d_in[0];
    // d_in[1]=up(3), d_in[2]=down(2) — fixed for this problem
    const float* h = (const float*)d_in[3];
    float* out = (float*)d_out;

    prep_kernel<<<(3 * S_PAD + 127) / 128, 128>>>(h);
    const int blocks = out_size / OUT_PER_BLK;   // 12582912 / 3072 = 4096
    resample_kernel<<<blocks, THREADS>>>(x, out);
}

// round 6
// speedup vs baseline: 1.1552x; 1.1203x over previous
#include <cuda_runtime.h>

typedef unsigned long long u64;

// Problem constants (fixed instance): up=3, down=2, N=8388608, F=1023
constexpr int NXP     = 4194304;  // x pairs (N/2)
constexpr int TAPS3   = 341;      // taps per polyphase branch
constexpr int A_PAD   = 172;      // pair-steps (171 real + 1 zero pad, mult of 4)
constexpr int RQ      = 4;        // consecutive q per thread (x3 phases = 12 outputs)
constexpr int THREADS = 256;
constexpr int QB      = THREADS * RQ;   // 1024 q per block
constexpr int TILE    = 1200;     // x pairs staged per block (span 1195 + pad)
constexpr int OUT_PER_BLK = 3 * QB;     // 3072 outputs

// Packed filter, all 3 phases per step: g_fpack[a*4 + v], v=0..2 phases, v=3 pad.
// Phase v: (p,rho) = (1,0),(0,1),(2,1). F2_v[a] = (hp[2a+rho], hp[2a+rho-1]),
// hp[j] = 3*h[p+3j], zero outside [0,341). For every phase the x window is the
// SAME pair index u = 85 + q - a  ->  one sliding window feeds 3 accumulators.
__device__ __align__(16) float2 g_fpack[A_PAD * 4];

__global__ void prep_kernel(const float* __restrict__ h) {
    int i = blockIdx.x * blockDim.x + threadIdx.x;
    if (i >= A_PAD * 4) return;
    int s = i >> 2, v = i & 3;
    float2 r = make_float2(0.0f, 0.0f);
    if (v < 3) {
        int p   = (v == 0) ? 1 : (v == 1 ? 0 : 2);
        int rho = (v == 0) ? 0 : 1;
        int jx = 2 * s + rho, jy = jx - 1;
        if (jx >= 0 && jx < TAPS3) r.x = 3.0f * h[p + 3 * jx];
        if (jy >= 0 && jy < TAPS3) r.y = 3.0f * h[p + 3 * jy];
    }
    g_fpack[i] = r;
}

// Byte-offset XOR swizzle: injects bits[7:11) into [3:7). For 32 lanes at 32B
// stride each lane-index bit maps to a distinct address bit in [3:7)
// (L0->b5, L1->b6, L2->b7->b3, L3->b8->b4, L4->b9->b5') -> conflict-free LDS.64.
__device__ __forceinline__ int swzb(int b) { return b ^ ((b >> 4) & 0x78); }

// Packed dual-fp32 FMA (sm_100+; ptxas emits FFMA2)
#define FFMA2(d, a, b) asm("fma.rn.f32x2 %0, %1, %2, %0;" : "+l"(d) : "l"(a), "l"(b))

__global__ __launch_bounds__(THREADS, 4)
void resample_kernel(const float* __restrict__ x, float* __restrict__ out) {
    // xs: swizzled x tile (9600B) ; reused as output staging (12288B)
    __shared__ __align__(16) u64 xs[1536];
    __shared__ __align__(16) u64 fsh[A_PAD * 4];   // 5504 B, uniform access

    const int tid = threadIdx.x;
    const int Q0  = blockIdx.x * QB;
    char* xsb = reinterpret_cast<char*>(xs);
    const char* fshb = reinterpret_cast<const char*>(fsh);

    // Stage filter (broadcast-read later at immediate offsets)
    {
        const u64* gf = reinterpret_cast<const u64*>(g_fpack);
        for (int i = tid; i < A_PAD * 4; i += THREADS) fsh[i] = gf[i];
    }

    // Stage x tile: tile[j] = X2[Q0 - 90 + j], zero outside [0, NXP)
    const float2* x2 = reinterpret_cast<const float2*>(x);
    for (int j = tid; j < TILE; j += THREADS) {
        int u = Q0 - 90 + j;
        float2 v = make_float2(0.0f, 0.0f);
        if (u >= 0 && u < NXP) v = __ldg(&x2[u]);
        *reinterpret_cast<float2*>(xsb + swzb(j * 8)) = v;
    }
    __syncthreads();

    // Thread handles q = Q0 + 4*tid + r, phases s=0,1,2.
    // Window W[r] = tile[175 + 4*tid + r - a] (tile base offset 4+171 = 175).
    u64 W[RQ], a0[RQ], a1[RQ], a2[RQ];
    const int base = (175 + RQ * tid) * 8;
#pragma unroll
    for (int r = 0; r < RQ; ++r) {
        a0[r] = a1[r] = a2[r] = 0ULL;
        W[r] = *reinterpret_cast<const u64*>(xsb + swzb(base + 8 * r));
    }

    const int rb = base - 8;   // refill byte offset at a=0
    for (int t = 0; t < A_PAD / 4; ++t) {
#pragma unroll
        for (int k = 0; k < 4; ++k) {
            const int a = t * 4 + k;
            // filter for step a: uniform address, immediate offsets
            const ulonglong2 f01 =
                *reinterpret_cast<const ulonglong2*>(fshb + 32 * a);
            const u64 f2v =
                *reinterpret_cast<const u64*>(fshb + 32 * a + 16);
#pragma unroll
            for (int r = 0; r < RQ; ++r) {
                FFMA2(a0[r], W[r], f01.x);
                FFMA2(a1[r], W[r], f01.y);
                FFMA2(a2[r], W[r], f2v);
            }
            // slide window down one pair
            const u64 nv =
                *reinterpret_cast<const u64*>(xsb + swzb(rb - 8 * a));
#pragma unroll
            for (int r = RQ - 1; r >= 1; --r) W[r] = W[r - 1];
            W[0] = nv;
        }
    }

    __syncthreads();   // done reading xs; reuse as output staging
    float* osh = reinterpret_cast<float*>(xs);
#pragma unroll
    for (int r = 0; r < RQ; ++r) {
        int mb = 12 * tid + 3 * r;   // local m = 3*(4*tid+r)+s
        float l0 = __uint_as_float((unsigned)(a0[r] & 0xffffffffull));
        float h0 = __uint_as_float((unsigned)(a0[r] >> 32));
        float l1 = __uint_as_float((unsigned)(a1[r] & 0xffffffffull));
        float h1 = __uint_as_float((unsigned)(a1[r] >> 32));
        float l2 = __uint_as_float((unsigned)(a2[r] & 0xffffffffull));
        float h2 = __uint_as_float((unsigned)(a2[r] >> 32));
        osh[mb + 0] = l0 + h0;
        osh[mb + 1] = l1 + h1;
        osh[mb + 2] = l2 + h2;
    }
    __syncthreads();

    // Coalesced float4 stream-out: block covers out[3*Q0 .. 3*Q0+3072)
    float4* dst = reinterpret_cast<float4*>(out + 3 * Q0);
    const float4* src = reinterpret_cast<const float4*>(osh);
    for (int i = tid; i < OUT_PER_BLK / 4; i += THREADS) dst[i] = src[i];
}

extern "C" void kernel_launch(void* const* d_in, const int* in_sizes, int n_in,
                              void* d_out, int out_size) {
    const float* x = (const float*)d_in[0];
    // d_in[1]=up(3), d_in[2]=down(2) — fixed for this problem
    const float* h = (const float*)d_in[3];
    float* out = (float*)d_out;

    prep_kernel<<<(A_PAD * 4 + 127) / 128, 128>>>(h);
    const int blocks = out_size / OUT_PER_BLK;   // 12582912 / 3072 = 4096
    resample_kernel<<<blocks, THREADS>>>(x, out);
}

// round 7
// speedup vs baseline: 1.2822x; 1.1099x over previous
#include <cuda_runtime.h>

typedef unsigned long long u64;

// Problem constants (fixed instance): up=3, down=2, N=8388608, F=1023
constexpr int NXP     = 4194304;  // x pairs (N/2)
constexpr int TAPS3   = 341;      // taps per polyphase branch
constexpr int A_PAD   = 172;      // pair-steps (171 real + 1 zero pad, mult of 4)
constexpr int NBODY   = A_PAD / 4;      // 43 bodies of 4 steps
constexpr int RQ      = 4;        // consecutive q per thread (x3 phases = 12 outputs)
constexpr int THREADS = 256;
constexpr int QB      = THREADS * RQ;   // 1024 q per block
constexpr int TILE    = 1204;     // x pairs staged (span + 8 bottom pad)
constexpr int OUT_PER_BLK = 3 * QB;     // 3072 outputs

// Packed filter, contiguous per step: g_fpack3[a*3 + v], v=0..2 phases.
// Phase v: (p,rho) = (1,0),(0,1),(2,1). F2_v[a] = (hp[2a+rho], hp[2a+rho-1]),
// hp[j] = 3*h[p+3j], zero outside [0,341). All 3 phases share the SAME x pair
// window u = 85 + q - a, so one sliding window feeds 3 accumulators.
// 24B/step -> one body (4 steps) = 96B, read as 6 broadcast LDS.128.
__device__ __align__(16) float2 g_fpack3[A_PAD * 3];

__global__ void prep_kernel(const float* __restrict__ h) {
    int i = blockIdx.x * blockDim.x + threadIdx.x;
    if (i >= A_PAD * 3) return;
    int s = i / 3, v = i % 3;
    int p   = (v == 0) ? 1 : (v == 1 ? 0 : 2);
    int rho = (v == 0) ? 0 : 1;
    int jx = 2 * s + rho, jy = jx - 1;
    float2 r = make_float2(0.0f, 0.0f);
    if (jx >= 0 && jx < TAPS3) r.x = 3.0f * h[p + 3 * jx];
    if (jy >= 0 && jy < TAPS3) r.y = 3.0f * h[p + 3 * jy];
    g_fpack3[i] = r;
}

// Byte-offset XOR swizzle: injects bits[7:11) into [3:7). For 32 lanes at 32B
// stride this yields conflict-free LDS.64. 3 ALU ops.
__device__ __forceinline__ int swzb(int b) { return b ^ ((b >> 4) & 0x78); }

// Packed dual-fp32 FMA (sm_100+; ptxas emits FFMA2)
#define FFMA2(d, a, b) asm("fma.rn.f32x2 %0, %1, %2, %0;" : "+l"(d) : "l"(a), "l"(b))

__global__ __launch_bounds__(THREADS, 3)
void resample_kernel(const float* __restrict__ x, float* __restrict__ out) {
    // xs: swizzled x tile (9632B); reused as output staging (12288B)
    __shared__ __align__(16) u64 xs[1536];
    __shared__ __align__(16) u64 fsh[A_PAD * 3];   // 4128 B, uniform broadcast

    const int tid = threadIdx.x;
    const int Q0  = blockIdx.x * QB;
    char* xsb = reinterpret_cast<char*>(xs);
    const char* fshb = reinterpret_cast<const char*>(fsh);

    // Stage filter
    {
        const u64* gf = reinterpret_cast<const u64*>(g_fpack3);
        for (int i = tid; i < A_PAD * 3; i += THREADS) fsh[i] = gf[i];
    }

    // Stage x tile: tile[j] = X2[Q0 - 94 + j], zero outside [0, NXP)
    const float2* x2 = reinterpret_cast<const float2*>(x);
    for (int j = tid; j < TILE; j += THREADS) {
        int u = Q0 - 94 + j;
        float2 v = make_float2(0.0f, 0.0f);
        if (u >= 0 && u < NXP) v = __ldg(&x2[u]);
        *reinterpret_cast<float2*>(xsb + swzb(j * 8)) = v;
    }
    __syncthreads();

    // Thread handles q = Q0 + 4*tid + r, phases v=0,1,2.
    // W[r] = tile[179 + 4*tid + r - a]  (= X2[Q0 + 85 + 4*tid + r - a])
    u64 W[RQ], a0[RQ], a1[RQ], a2[RQ];
    const int base = (179 + RQ * tid) * 8;
#pragma unroll
    for (int r = 0; r < RQ; ++r) {
        a0[r] = a1[r] = a2[r] = 0ULL;
        W[r] = *reinterpret_cast<const u64*>(xsb + swzb(base + 8 * r));
    }

    // Software-pipelined refill: pre[] holds the current body's 4 refills.
    int pb = base - 8;                 // refill byte offset for a = 0
    u64 pre[4];
#pragma unroll
    for (int k = 0; k < 4; ++k)
        pre[k] = *reinterpret_cast<const u64*>(xsb + swzb(pb - 8 * k));
    pb -= 32;

    for (int t = 0; t < NBODY; ++t) {
        // Batched broadcast filter loads for this body (96B, 6x LDS.128)
        const ulonglong2* fb =
            reinterpret_cast<const ulonglong2*>(fshb + 96 * t);
        const ulonglong2 f0 = fb[0], f1 = fb[1], f2 = fb[2],
                         f3 = fb[3], f4 = fb[4], f5 = fb[5];

        // Prefetch next body's refills (final iteration reads pad, unused)
        u64 nxt[4];
#pragma unroll
        for (int k = 0; k < 4; ++k)
            nxt[k] = *reinterpret_cast<const u64*>(xsb + swzb(pb - 8 * k));
        pb -= 32;

        // step 0: filter u64s (f0.x, f0.y, f1.x)
#pragma unroll
        for (int r = 0; r < RQ; ++r) {
            FFMA2(a0[r], W[r], f0.x);
            FFMA2(a1[r], W[r], f0.y);
            FFMA2(a2[r], W[r], f1.x);
        }
        W[3] = W[2]; W[2] = W[1]; W[1] = W[0]; W[0] = pre[0];

        // step 1: (f1.y, f2.x, f2.y)
#pragma unroll
        for (int r = 0; r < RQ; ++r) {
            FFMA2(a0[r], W[r], f1.y);
            FFMA2(a1[r], W[r], f2.x);
            FFMA2(a2[r], W[r], f2.y);
        }
        W[3] = W[2]; W[2] = W[1]; W[1] = W[0]; W[0] = pre[1];

        // step 2: (f3.x, f3.y, f4.x)
#pragma unroll
        for (int r = 0; r < RQ; ++r) {
            FFMA2(a0[r], W[r], f3.x);
            FFMA2(a1[r], W[r], f3.y);
            FFMA2(a2[r], W[r], f4.x);
        }
        W[3] = W[2]; W[2] = W[1]; W[1] = W[0]; W[0] = pre[2];

        // step 3: (f4.y, f5.x, f5.y)
#pragma unroll
        for (int r = 0; r < RQ; ++r) {
            FFMA2(a0[r], W[r], f4.y);
            FFMA2(a1[r], W[r], f5.x);
            FFMA2(a2[r], W[r], f5.y);
        }
        W[3] = W[2]; W[2] = W[1]; W[1] = W[0]; W[0] = pre[3];

#pragma unroll
        for (int k = 0; k < 4; ++k) pre[k] = nxt[k];
    }

    __syncthreads();   // done reading xs; reuse as output staging
    float* osh = reinterpret_cast<float*>(xs);
#pragma unroll
    for (int r = 0; r < RQ; ++r) {
        int mb = 12 * tid + 3 * r;   // local m = 3*(4*tid+r)+v
        float l0 = __uint_as_float((unsigned)(a0[r] & 0xffffffffull));
        float h0 = __uint_as_float((unsigned)(a0[r] >> 32));
        float l1 = __uint_as_float((unsigned)(a1[r] & 0xffffffffull));
        float h1 = __uint_as_float((unsigned)(a1[r] >> 32));
        float l2 = __uint_as_float((unsigned)(a2[r] & 0xffffffffull));
        float h2 = __uint_as_float((unsigned)(a2[r] >> 32));
        osh[mb + 0] = l0 + h0;
        osh[mb + 1] = l1 + h1;
        osh[mb + 2] = l2 + h2;
    }
    __syncthreads();

    // Coalesced float4 stream-out: block covers out[3*Q0 .. 3*Q0+3072)
    float4* dst = reinterpret_cast<float4*>(out + 3 * Q0);
    const float4* src = reinterpret_cast<const float4*>(osh);
    for (int i = tid; i < OUT_PER_BLK / 4; i += THREADS) dst[i] = src[i];
}

extern "C" void kernel_launch(void* const* d_in, const int* in_sizes, int n_in,
                              void* d_out, int out_size) {
    const float* x = (const float*)d_in[0];
    // d_in[1]=up(3), d_in[2]=down(2) — fixed for this problem
    const float* h = (const float*)d_in[3];
    float* out = (float*)d_out;

    prep_kernel<<<(A_PAD * 3 + 127) / 128, 128>>>(h);
    const int blocks = out_size / OUT_PER_BLK;   // 12582912 / 3072 = 4096
    resample_kernel<<<blocks, THREADS>>>(x, out);
}